// round 4
// baseline (speedup 1.0000x reference)
#include <cuda_runtime.h>

// Problem constants (fixed shapes for this problem instance)
constexpr int N_   = 2048;   // nodes
constexpr int F_   = 512;    // features
constexpr int M_   = 10;     // chebyshev order
constexpr int Q_   = 64;     // quadrature points
constexpr int ELL  = 64;     // max nnz per row of L_hat (expected ~16, 12-sigma safe)
constexpr float THRESH = 1e-5f;
constexpr float TAIL_TOL = 1e-7f;   // |H entry| error bound for dropped Chebyshev terms

// Scratch: __device__ globals (sanctioned; no cudaMalloc allowed)
__device__ float g_T[3][N_ * N_];       // ping-pong Chebyshev T_k buffers (3 x 16.8 MB)
__device__ float g_H[N_ * N_];          // accumulated heat kernel
__device__ float g_c[N_ * (M_ + 1)];    // per-node Chebyshev coefficients
__device__ float g_Lval[N_ * ELL];      // ELL sparse L_hat values
__device__ int   g_Lcol[N_ * ELL];      // ELL sparse L_hat column indices
__device__ int   g_Lcnt[N_];            // nnz per row
__device__ int   g_need[M_ + 1];        // adaptive step-skip flags (suffix criterion)

// ---------------------------------------------------------------------------
// Kernel 1: per-node Chebyshev-Gauss quadrature coefficients c[i, 0..M]
// ---------------------------------------------------------------------------
__global__ void k_coeff(const float* __restrict__ t, const float* __restrict__ eigmax) {
    int i = blockIdx.x * blockDim.x + threadIdx.x;
    if (i >= N_) return;
    float s  = expf(t[i]);
    float em = eigmax[0];
    float acc[M_ + 1];
#pragma unroll
    for (int k = 0; k <= M_; k++) acc[k] = 0.0f;

    const float PI = 3.14159265358979323846f;
    for (int q = 0; q < Q_; q++) {
        float theta = PI * ((float)q + 0.5f) / (float)Q_;
        float ct    = cosf(theta);
        float lam   = em * 0.5f * (ct + 1.0f);
        float w     = expf(-s * lam);
        float ckm1 = 1.0f;
        float ck   = ct;
        acc[0] += w;
        acc[1] += w * ck;
#pragma unroll
        for (int k = 2; k <= M_; k++) {
            float cn = 2.0f * ct * ck - ckm1;
            ckm1 = ck; ck = cn;
            acc[k] += w * cn;
        }
    }
    float scale = 2.0f / (float)Q_;
#pragma unroll
    for (int k = 0; k <= M_; k++) {
        float v = scale * acc[k];
        if (k == 0) v *= 0.5f;
        g_c[i * (M_ + 1) + k] = v;
    }
}

// ---------------------------------------------------------------------------
// Kernel 1b: adaptive step flags. need[k] = 1 iff dropping all terms j>=k
// would perturb H entries by more than TAIL_TOL (|T_j| entries <= 1 on the
// scaled spectrum, so the entrywise error of truncation at k is bounded by
// sum_{j>=k} max_i |c[i,j]|). Flags are suffix-monotone by construction, so
// the recurrence stays valid. One block.
// ---------------------------------------------------------------------------
__global__ void k_flags() {
    int tid = threadIdx.x;
    float local[M_ + 1];
#pragma unroll
    for (int k = 0; k <= M_; k++) local[k] = 0.0f;
    for (int i = tid; i < N_; i += 256) {
#pragma unroll
        for (int k = 2; k <= M_; k++)
            local[k] = fmaxf(local[k], fabsf(g_c[i * (M_ + 1) + k]));
    }
#pragma unroll
    for (int k = 2; k <= M_; k++) {
#pragma unroll
        for (int o = 16; o > 0; o >>= 1)
            local[k] = fmaxf(local[k], __shfl_xor_sync(0xffffffffu, local[k], o));
    }
    __shared__ float red[8][M_ + 1];
    if ((tid & 31) == 0) {
#pragma unroll
        for (int k = 2; k <= M_; k++) red[tid >> 5][k] = local[k];
    }
    __syncthreads();
    if (tid == 0) {
        float tail = 0.0f;
        for (int k = M_; k >= 2; k--) {
            float m = 0.0f;
#pragma unroll
            for (int w = 0; w < 8; w++) m = fmaxf(m, red[w][k]);
            tail += m;
            g_need[k] = (tail > TAIL_TOL) ? 1 : 0;
        }
    }
}

// ---------------------------------------------------------------------------
// Kernel 2: extract sparse (ELL) structure of L_hat = (2/eigmax)*P_n - I.
// ---------------------------------------------------------------------------
__global__ void k_build(const float* __restrict__ P, const float* __restrict__ eigmax) {
    int warps_per_blk = blockDim.x >> 5;
    int row  = blockIdx.x * warps_per_blk + (threadIdx.x >> 5);
    int lane = threadIdx.x & 31;
    if (row >= N_) return;
    float sc = 2.0f / eigmax[0];
    int cnt = 0;
    for (int base = 0; base < N_; base += 32) {
        int col = base + lane;
        float v = sc * P[(size_t)row * N_ + col] - (col == row ? 1.0f : 0.0f);
        unsigned m = __ballot_sync(0xffffffffu, v != 0.0f);
        if (v != 0.0f) {
            int pos = cnt + __popc(m & ((1u << lane) - 1u));
            if (pos < ELL) {
                g_Lval[row * ELL + pos] = v;
                g_Lcol[row * ELL + pos] = col;
            }
        }
        cnt += __popc(m);
    }
    if (lane == 0) g_Lcnt[row] = cnt < ELL ? cnt : ELL;
}

// ---------------------------------------------------------------------------
// Kernel 3: init T0 = I, T1 = L_hat (dense), H = c0*I + c1*L_hat
// ---------------------------------------------------------------------------
__global__ void k_init(const float* __restrict__ P, const float* __restrict__ eigmax) {
    int idx = blockIdx.x * blockDim.x + threadIdx.x;
    if (idx >= N_ * N_ / 4) return;
    int i    = idx >> 9;
    int c4   = idx & 511;
    int col0 = c4 * 4;
    float sc = 2.0f / eigmax[0];

    float4 p = reinterpret_cast<const float4*>(P)[idx];
    float4 l = make_float4(sc * p.x, sc * p.y, sc * p.z, sc * p.w);
    float4 t0 = make_float4(0.f, 0.f, 0.f, 0.f);
    int d = i - col0;
    if (d >= 0 && d < 4) {
        reinterpret_cast<float*>(&l)[d]  -= 1.0f;
        reinterpret_cast<float*>(&t0)[d]  = 1.0f;
    }
    reinterpret_cast<float4*>(g_T[1])[idx] = l;
    reinterpret_cast<float4*>(g_T[0])[idx] = t0;

    float c0 = g_c[i * (M_ + 1) + 0];
    float c1 = g_c[i * (M_ + 1) + 1];
    float4 h = make_float4(c0 * t0.x + c1 * l.x,
                           c0 * t0.y + c1 * l.y,
                           c0 * t0.z + c1 * l.z,
                           c0 * t0.w + c1 * l.w);
    reinterpret_cast<float4*>(g_H)[idx] = h;
}

// ---------------------------------------------------------------------------
// Kernel 4: one Chebyshev recurrence step (fused SpMM + H accumulate).
// Early-exits if this term (and all later ones) are below TAIL_TOL.
// ---------------------------------------------------------------------------
__global__ void __launch_bounds__(512) k_step(int ip, int ic, int inew, int k) {
    if (!g_need[k]) return;

    const float* __restrict__ Tprev = g_T[ip];
    const float* __restrict__ Tcur  = g_T[ic];
    float*       __restrict__ Tnew  = g_T[inew];

    int row = blockIdx.x;
    __shared__ float sval[ELL];
    __shared__ int   scol[ELL];
    int cnt = g_Lcnt[row];
    if (threadIdx.x < ELL) {
        sval[threadIdx.x] = g_Lval[row * ELL + threadIdx.x];
        scol[threadIdx.x] = g_Lcol[row * ELL + threadIdx.x];
    }
    __syncthreads();

    float ck = g_c[row * (M_ + 1) + k];
    int c4 = threadIdx.x;
    const float4* Tc4 = reinterpret_cast<const float4*>(Tcur);

    int o = row * (N_ / 4) + c4;
    // hoist independent loads to overlap with the gather loop's L2 latency
    float4 p = reinterpret_cast<const float4*>(Tprev)[o];
    float4 h = reinterpret_cast<float4*>(g_H)[o];

    float4 acc = make_float4(0.f, 0.f, 0.f, 0.f);
#pragma unroll 8
    for (int tnz = 0; tnz < cnt; tnz++) {
        float v = sval[tnz];
        int   j = scol[tnz];
        float4 b = __ldg(&Tc4[j * (N_ / 4) + c4]);
        acc.x = fmaf(v, b.x, acc.x);
        acc.y = fmaf(v, b.y, acc.y);
        acc.z = fmaf(v, b.z, acc.z);
        acc.w = fmaf(v, b.w, acc.w);
    }
    float4 tn = make_float4(2.0f * acc.x - p.x, 2.0f * acc.y - p.y,
                            2.0f * acc.z - p.z, 2.0f * acc.w - p.w);
    reinterpret_cast<float4*>(Tnew)[o] = tn;

    h.x = fmaf(ck, tn.x, h.x);
    h.y = fmaf(ck, tn.y, h.y);
    h.z = fmaf(ck, tn.z, h.z);
    h.w = fmaf(ck, tn.w, h.w);
    reinterpret_cast<float4*>(g_H)[o] = h;
}

// ---------------------------------------------------------------------------
// Kernel 5: out = threshold(H) @ x.  128x64x16 tiles, 256 threads, 8x4
// microtile, double-buffered smem. Threshold applied on the A load.
// ---------------------------------------------------------------------------
constexpr int BM = 128, BN = 64, BK = 16;

__global__ void __launch_bounds__(256) k_gemm(const float* __restrict__ X,
                                              float* __restrict__ out) {
    __shared__ float As[2][BK][BM + 4];   // As[buf][k][i], 2-way-conflict pad
    __shared__ float Bs[2][BK][BN];       // Bs[buf][k][f]

    int f0 = blockIdx.x * BN;
    int i0 = blockIdx.y * BM;
    int tid = threadIdx.x;
    int tx = tid & 15;        // 0..15 -> 4 output cols each
    int ty = tid >> 4;        // 0..15 -> 8 output rows each

    float acc[8][4];
#pragma unroll
    for (int r = 0; r < 8; r++)
#pragma unroll
        for (int s = 0; s < 4; s++) acc[r][s] = 0.0f;

    // A tile: 128x16 = 512 float4, 2 per thread. fi -> row=fi>>2, k4=(fi&3)*4
    // B tile: 16x64  = 256 float4, 1 per thread. tid -> k=tid>>4, f=(tid&15)*4
    float4 aR[2], bR;
    int b_k  = tid >> 4;
    int b_f0 = (tid & 15) << 2;

    auto loadG = [&](int kt) {
#pragma unroll
        for (int s = 0; s < 2; s++) {
            int fi = tid + s * 256;
            int r  = fi >> 2;
            int k4 = (fi & 3) << 2;
            float4 a = *reinterpret_cast<const float4*>(
                &g_H[(size_t)(i0 + r) * N_ + kt + k4]);
            a.x = (a.x < THRESH) ? 0.0f : a.x;
            a.y = (a.y < THRESH) ? 0.0f : a.y;
            a.z = (a.z < THRESH) ? 0.0f : a.z;
            a.w = (a.w < THRESH) ? 0.0f : a.w;
            aR[s] = a;
        }
        bR = *reinterpret_cast<const float4*>(
            &X[(size_t)(kt + b_k) * F_ + f0 + b_f0]);
    };
    auto stS = [&](int buf) {
#pragma unroll
        for (int s = 0; s < 2; s++) {
            int fi = tid + s * 256;
            int r  = fi >> 2;
            int k4 = (fi & 3) << 2;
            As[buf][k4 + 0][r] = aR[s].x;
            As[buf][k4 + 1][r] = aR[s].y;
            As[buf][k4 + 2][r] = aR[s].z;
            As[buf][k4 + 3][r] = aR[s].w;
        }
        *reinterpret_cast<float4*>(&Bs[buf][b_k][b_f0]) = bR;
    };

    loadG(0);
    stS(0);
    __syncthreads();

    int buf = 0;
    for (int kt = 0; kt < N_; kt += BK) {
        if (kt + BK < N_) loadG(kt + BK);
#pragma unroll
        for (int kk = 0; kk < BK; kk++) {
            float4 a0 = *reinterpret_cast<const float4*>(&As[buf][kk][ty * 8]);
            float4 a1 = *reinterpret_cast<const float4*>(&As[buf][kk][ty * 8 + 4]);
            float4 b  = *reinterpret_cast<const float4*>(&Bs[buf][kk][tx * 4]);
            const float* ap0 = reinterpret_cast<const float*>(&a0);
            const float* ap1 = reinterpret_cast<const float*>(&a1);
            const float* bp  = reinterpret_cast<const float*>(&b);
#pragma unroll
            for (int r = 0; r < 4; r++)
#pragma unroll
                for (int s = 0; s < 4; s++) {
                    acc[r][s]     = fmaf(ap0[r], bp[s], acc[r][s]);
                    acc[r + 4][s] = fmaf(ap1[r], bp[s], acc[r + 4][s]);
                }
        }
        if (kt + BK < N_) {
            stS(buf ^ 1);
            __syncthreads();
            buf ^= 1;
        }
    }

#pragma unroll
    for (int r = 0; r < 8; r++) {
        int gi = (r < 4) ? (ty * 8 + r) : (ty * 8 + r);
        float4 v = make_float4(acc[r][0], acc[r][1], acc[r][2], acc[r][3]);
        reinterpret_cast<float4*>(
            &out[(size_t)(i0 + gi) * F_ + f0 + tx * 4])[0] = v;
    }
}

// ---------------------------------------------------------------------------
// Kernel 6: second reference output is t itself -> copy to tail of d_out
// ---------------------------------------------------------------------------
__global__ void k_copy_t(const float* __restrict__ t, float* __restrict__ out) {
    int i = blockIdx.x * blockDim.x + threadIdx.x;
    if (i < N_) out[(size_t)N_ * F_ + i] = t[i];
}

// ---------------------------------------------------------------------------
extern "C" void kernel_launch(void* const* d_in, const int* in_sizes, int n_in,
                              void* d_out, int out_size) {
    const float* x   = (const float*)d_in[0];   // [N, F]
    const float* P   = (const float*)d_in[1];   // [N, N]
    const float* t   = (const float*)d_in[2];   // [N]
    const float* eig = (const float*)d_in[3];   // [1]
    float* out = (float*)d_out;

    k_coeff<<<(N_ + 255) / 256, 256>>>(t, eig);
    k_flags<<<1, 256>>>();
    k_build<<<N_ / 8, 256>>>(P, eig);            // 8 warps/block, 1 warp/row
    k_init<<<(N_ * N_ / 4 + 255) / 256, 256>>>(P, eig);

    int ip = 0, ic = 1, inew = 2;
    for (int k = 2; k <= M_; k++) {
        k_step<<<N_, 512>>>(ip, ic, inew, k);
        int tmp = ip; ip = ic; ic = inew; inew = tmp;
    }

    dim3 gg(F_ / BN, N_ / BM);
    k_gemm<<<gg, 256>>>(x, out);

    if (out_size >= N_ * F_ + N_)
        k_copy_t<<<(N_ + 255) / 256, 256>>>(t, out);
}

// round 5
// speedup vs baseline: 3.6290x; 3.6290x over previous
#include <cuda_runtime.h>

// Problem constants (fixed shapes for this problem instance)
constexpr int N_   = 2048;   // nodes
constexpr int F_   = 512;    // features
constexpr int F4   = F_ / 4; // float4 groups per row (128)
constexpr int M_   = 10;     // chebyshev order
constexpr int Q_   = 64;     // quadrature points
constexpr int ELL  = 64;     // max nnz per row of L_hat (expected ~16, 12-sigma safe)
constexpr float TAIL_TOL = 1e-7f;   // drop tolerance for trailing Chebyshev terms

// Scratch: __device__ globals (sanctioned; no cudaMalloc allowed)
__device__ float g_Y[3][N_ * F_];       // ping-pong Chebyshev y_k = T_k(L_hat) x  (3 x 4 MB)
__device__ float g_c[N_ * (M_ + 1)];    // per-node Chebyshev coefficients
__device__ float g_Lval[N_ * ELL];      // ELL sparse L_hat values
__device__ int   g_Lcol[N_ * ELL];      // ELL sparse L_hat column indices
__device__ int   g_Lcnt[N_];            // nnz per row
__device__ int   g_need[M_ + 1];        // adaptive step-skip flags (suffix criterion)

// ---------------------------------------------------------------------------
// Kernel 1: per-node Chebyshev-Gauss quadrature coefficients c[i, 0..M]
// ---------------------------------------------------------------------------
__global__ void k_coeff(const float* __restrict__ t, const float* __restrict__ eigmax) {
    int i = blockIdx.x * blockDim.x + threadIdx.x;
    if (i >= N_) return;
    float s  = expf(t[i]);
    float em = eigmax[0];
    float acc[M_ + 1];
#pragma unroll
    for (int k = 0; k <= M_; k++) acc[k] = 0.0f;

    const float PI = 3.14159265358979323846f;
    for (int q = 0; q < Q_; q++) {
        float theta = PI * ((float)q + 0.5f) / (float)Q_;
        float ct    = cosf(theta);
        float lam   = em * 0.5f * (ct + 1.0f);
        float w     = expf(-s * lam);
        float ckm1 = 1.0f;
        float ck   = ct;
        acc[0] += w;
        acc[1] += w * ck;
#pragma unroll
        for (int k = 2; k <= M_; k++) {
            float cn = 2.0f * ct * ck - ckm1;
            ckm1 = ck; ck = cn;
            acc[k] += w * cn;
        }
    }
    float scale = 2.0f / (float)Q_;
#pragma unroll
    for (int k = 0; k <= M_; k++) {
        float v = scale * acc[k];
        if (k == 0) v *= 0.5f;
        g_c[i * (M_ + 1) + k] = v;
    }
}

// ---------------------------------------------------------------------------
// Kernel 1b: adaptive step flags. need[k] = 1 iff dropping all terms j>=k
// would perturb outputs beyond TAIL_TOL (|T_j| spectral bound <= 1, so the
// truncation error at k is bounded by sum_{j>=k} max_i |c[i,j]|). Flags are
// suffix-monotone, so the recurrence stays valid. One block.
// ---------------------------------------------------------------------------
__global__ void k_flags() {
    int tid = threadIdx.x;
    float local[M_ + 1];
#pragma unroll
    for (int k = 0; k <= M_; k++) local[k] = 0.0f;
    for (int i = tid; i < N_; i += 256) {
#pragma unroll
        for (int k = 2; k <= M_; k++)
            local[k] = fmaxf(local[k], fabsf(g_c[i * (M_ + 1) + k]));
    }
#pragma unroll
    for (int k = 2; k <= M_; k++) {
#pragma unroll
        for (int o = 16; o > 0; o >>= 1)
            local[k] = fmaxf(local[k], __shfl_xor_sync(0xffffffffu, local[k], o));
    }
    __shared__ float red[8][M_ + 1];
    if ((tid & 31) == 0) {
#pragma unroll
        for (int k = 2; k <= M_; k++) red[tid >> 5][k] = local[k];
    }
    __syncthreads();
    if (tid == 0) {
        float tail = 0.0f;
        for (int k = M_; k >= 2; k--) {
            float m = 0.0f;
#pragma unroll
            for (int w = 0; w < 8; w++) m = fmaxf(m, red[w][k]);
            tail += m;
            g_need[k] = (tail > TAIL_TOL) ? 1 : 0;
        }
    }
}

// ---------------------------------------------------------------------------
// Kernel 2: extract sparse (ELL) structure of L_hat = (2/eigmax)*P_n - I.
// One warp per row; deterministic ballot-based ordered compaction.
// ---------------------------------------------------------------------------
__global__ void k_build(const float* __restrict__ P, const float* __restrict__ eigmax) {
    int warps_per_blk = blockDim.x >> 5;
    int row  = blockIdx.x * warps_per_blk + (threadIdx.x >> 5);
    int lane = threadIdx.x & 31;
    if (row >= N_) return;
    float sc = 2.0f / eigmax[0];
    int cnt = 0;
    for (int base = 0; base < N_; base += 32) {
        int col = base + lane;
        float v = sc * P[(size_t)row * N_ + col] - (col == row ? 1.0f : 0.0f);
        unsigned m = __ballot_sync(0xffffffffu, v != 0.0f);
        if (v != 0.0f) {
            int pos = cnt + __popc(m & ((1u << lane) - 1u));
            if (pos < ELL) {
                g_Lval[row * ELL + pos] = v;
                g_Lcol[row * ELL + pos] = col;
            }
        }
        cnt += __popc(m);
    }
    if (lane == 0) g_Lcnt[row] = cnt < ELL ? cnt : ELL;
}

// ---------------------------------------------------------------------------
// Kernel 3: first recurrence level on x directly.
//   y0 = x ; y1 = L_hat @ x ; out = c0*x + c1*y1
// One block per row, 128 threads, one float4 feature-group per thread.
// ---------------------------------------------------------------------------
__global__ void __launch_bounds__(128) k_first(const float* __restrict__ x,
                                               float* __restrict__ out) {
    int row = blockIdx.x;
    __shared__ float sval[ELL];
    __shared__ int   scol[ELL];
    int cnt = g_Lcnt[row];
    if (threadIdx.x < ELL && threadIdx.x < cnt) {
        sval[threadIdx.x] = g_Lval[row * ELL + threadIdx.x];
        scol[threadIdx.x] = g_Lcol[row * ELL + threadIdx.x];
    }
    __syncthreads();

    int c4 = threadIdx.x;                        // 0..127
    const float4* X4 = reinterpret_cast<const float4*>(x);
    int o = row * F4 + c4;
    float4 xv = X4[o];

    float4 acc = make_float4(0.f, 0.f, 0.f, 0.f);
#pragma unroll 8
    for (int tnz = 0; tnz < cnt; tnz++) {
        float v = sval[tnz];
        int   j = scol[tnz];
        float4 b = __ldg(&X4[j * F4 + c4]);
        acc.x = fmaf(v, b.x, acc.x);
        acc.y = fmaf(v, b.y, acc.y);
        acc.z = fmaf(v, b.z, acc.z);
        acc.w = fmaf(v, b.w, acc.w);
    }

    reinterpret_cast<float4*>(g_Y[0])[o] = xv;    // y0 = x
    reinterpret_cast<float4*>(g_Y[1])[o] = acc;   // y1 = L_hat x

    float c0 = g_c[row * (M_ + 1) + 0];
    float c1 = g_c[row * (M_ + 1) + 1];
    float4 ov = make_float4(fmaf(c1, acc.x, c0 * xv.x),
                            fmaf(c1, acc.y, c0 * xv.y),
                            fmaf(c1, acc.z, c0 * xv.z),
                            fmaf(c1, acc.w, c0 * xv.w));
    reinterpret_cast<float4*>(out)[o] = ov;
}

// ---------------------------------------------------------------------------
// Kernel 4: one Chebyshev recurrence step on the feature matrix.
//   y_new = 2 * L_hat @ y_cur - y_prev ; out += c[:,k] * y_new
// Early-exits if this term (and all later ones) are below TAIL_TOL.
// ---------------------------------------------------------------------------
__global__ void __launch_bounds__(128) k_step_f(int ip, int ic, int inew, int k,
                                                float* __restrict__ out) {
    if (!g_need[k]) return;

    const float* __restrict__ Yprev = g_Y[ip];
    const float* __restrict__ Ycur  = g_Y[ic];
    float*       __restrict__ Ynew  = g_Y[inew];

    int row = blockIdx.x;
    __shared__ float sval[ELL];
    __shared__ int   scol[ELL];
    int cnt = g_Lcnt[row];
    if (threadIdx.x < ELL && threadIdx.x < cnt) {
        sval[threadIdx.x] = g_Lval[row * ELL + threadIdx.x];
        scol[threadIdx.x] = g_Lcol[row * ELL + threadIdx.x];
    }
    __syncthreads();

    float ck = g_c[row * (M_ + 1) + k];
    int c4 = threadIdx.x;
    const float4* Yc4 = reinterpret_cast<const float4*>(Ycur);
    int o = row * F4 + c4;

    // hoist independent loads to overlap with the gather loop's L2 latency
    float4 p  = reinterpret_cast<const float4*>(Yprev)[o];
    float4 ov = reinterpret_cast<float4*>(out)[o];

    float4 acc = make_float4(0.f, 0.f, 0.f, 0.f);
#pragma unroll 8
    for (int tnz = 0; tnz < cnt; tnz++) {
        float v = sval[tnz];
        int   j = scol[tnz];
        float4 b = __ldg(&Yc4[j * F4 + c4]);
        acc.x = fmaf(v, b.x, acc.x);
        acc.y = fmaf(v, b.y, acc.y);
        acc.z = fmaf(v, b.z, acc.z);
        acc.w = fmaf(v, b.w, acc.w);
    }
    float4 yn = make_float4(2.0f * acc.x - p.x, 2.0f * acc.y - p.y,
                            2.0f * acc.z - p.z, 2.0f * acc.w - p.w);
    reinterpret_cast<float4*>(Ynew)[o] = yn;

    ov.x = fmaf(ck, yn.x, ov.x);
    ov.y = fmaf(ck, yn.y, ov.y);
    ov.z = fmaf(ck, yn.z, ov.z);
    ov.w = fmaf(ck, yn.w, ov.w);
    reinterpret_cast<float4*>(out)[o] = ov;
}

// ---------------------------------------------------------------------------
// Kernel 5: second reference output is t itself -> copy to tail of d_out
// ---------------------------------------------------------------------------
__global__ void k_copy_t(const float* __restrict__ t, float* __restrict__ out) {
    int i = blockIdx.x * blockDim.x + threadIdx.x;
    if (i < N_) out[(size_t)N_ * F_ + i] = t[i];
}

// ---------------------------------------------------------------------------
extern "C" void kernel_launch(void* const* d_in, const int* in_sizes, int n_in,
                              void* d_out, int out_size) {
    const float* x   = (const float*)d_in[0];   // [N, F]
    const float* P   = (const float*)d_in[1];   // [N, N]
    const float* t   = (const float*)d_in[2];   // [N]
    const float* eig = (const float*)d_in[3];   // [1]
    float* out = (float*)d_out;

    k_coeff<<<(N_ + 255) / 256, 256>>>(t, eig);
    k_flags<<<1, 256>>>();
    k_build<<<N_ / 8, 256>>>(P, eig);            // 8 warps/block, 1 warp/row

    k_first<<<N_, 128>>>(x, out);                // y0=x, y1=Lx, out=c0 x + c1 y1

    int ip = 0, ic = 1, inew = 2;
    for (int k = 2; k <= M_; k++) {
        k_step_f<<<N_, 128>>>(ip, ic, inew, k, out);
        int tmp = ip; ip = ic; ic = inew; inew = tmp;
    }

    if (out_size >= N_ * F_ + N_)
        k_copy_t<<<(N_ + 255) / 256, 256>>>(t, out);
}